// round 2
// baseline (speedup 1.0000x reference)
#include <cuda_runtime.h>

// Problem constants
#define SS   128      // MSA depth S
#define NRES 256      // N residues
#define DD   64       // msa dim
#define HH_  32       // proj dim H
#define PP   64       // output dim P
#define M_TOT 8192    // N*H
#define KK2  1024     // H*H

// Device scratch (allocation-free rule: __device__ globals)
__device__ float g_A[SS * M_TOT];                 // [s][i*32+h], (xWa+ba)*mask/denom[i]   4 MB
__device__ float g_B[SS * M_TOT];                 // [s][j*32+k], (xWb+bb)*mask            4 MB
__device__ float g_outer[(size_t)65536 * KK2];    // [(i*256+j)][h*32+k]                 256 MB
__device__ float g_invden[NRES];

// ---------------- f32x2 packed helpers (sm_103a FFMA2 path) ----------------
__device__ __forceinline__ unsigned long long pack2(float lo, float hi) {
    unsigned long long r;
    asm("mov.b64 %0, {%1, %2};" : "=l"(r) : "f"(lo), "f"(hi));
    return r;
}
__device__ __forceinline__ void unpack2(unsigned long long v, float& lo, float& hi) {
    asm("mov.b64 {%0, %1}, %2;" : "=f"(lo), "=f"(hi) : "l"(v));
}
__device__ __forceinline__ void ffma2(unsigned long long& d, unsigned long long a, unsigned long long b) {
    asm("fma.rn.f32x2 %0, %1, %2, %0;" : "+l"(d) : "l"(a), "l"(b));
}

// ---------------- denom: denom[i] = max(sum_s mask[s,i], 1) ----------------
__global__ void k_denom(const float* __restrict__ mask) {
    int i = threadIdx.x;  // 256 threads
    float s = 0.f;
    #pragma unroll 8
    for (int t = 0; t < SS; ++t) s += mask[t * NRES + i];
    g_invden[i] = 1.0f / fmaxf(s, 1.0f);
}

// ---------------- prep: LN + dual projection + mask + denom fold ----------------
// 256 threads = 8 warps, one row (s,i) per warp.
__global__ void __launch_bounds__(256) k_prep(
    const float* __restrict__ x, const float* __restrict__ mask,
    const float* __restrict__ gamma, const float* __restrict__ beta,
    const float* __restrict__ Wa, const float* __restrict__ ba,
    const float* __restrict__ Wb, const float* __restrict__ bb)
{
    __shared__ float sx[8][64];
    int warp = threadIdx.x >> 5, lane = threadIdx.x & 31;
    int row = blockIdx.x * 8 + warp;          // row = s*256 + i
    const float* xr = x + (size_t)row * DD;

    float v0 = xr[lane], v1 = xr[lane + 32];
    float sum = v0 + v1;
    #pragma unroll
    for (int o = 16; o; o >>= 1) sum += __shfl_xor_sync(~0u, sum, o);
    float mu = sum * (1.0f / 64.0f);
    float d0 = v0 - mu, d1 = v1 - mu;
    float vs = d0 * d0 + d1 * d1;
    #pragma unroll
    for (int o = 16; o; o >>= 1) vs += __shfl_xor_sync(~0u, vs, o);
    float rstd = rsqrtf(vs * (1.0f / 64.0f) + 1e-5f);
    sx[warp][lane]      = d0 * rstd * gamma[lane]      + beta[lane];
    sx[warp][lane + 32] = d1 * rstd * gamma[lane + 32] + beta[lane + 32];
    __syncwarp();

    int s = row >> 8, i = row & 255;
    float m = mask[s * NRES + i];
    float a = ba[lane], b = bb[lane];
    #pragma unroll
    for (int d = 0; d < 64; ++d) {
        float xv = sx[warp][d];
        a = fmaf(xv, Wa[d * HH_ + lane], a);
        b = fmaf(xv, Wb[d * HH_ + lane], b);
    }
    a *= m * g_invden[i];
    b *= m;
    g_A[s * M_TOT + i * HH_ + lane] = a;
    g_B[s * M_TOT + i * HH_ + lane] = b;
}

// ---------------- GEMM1: C[m,n] = sum_s A[s,m]*B[s,n], tile 128x128, K=128 ----------------
// Writes directly into g_outer in (i*256+j, h*32+k) permuted layout.
__global__ void __launch_bounds__(256) k_gemm1() {
    extern __shared__ float sm[];              // 128 KB dynamic
    float* sA = sm;                            // [k][m] 128x128
    float* sB = sm + 128 * 128;                // [k][n] 128x128
    int tid = threadIdx.x;
    int bm = blockIdx.x, bn = blockIdx.y;

    const float* gA = g_A + bm * 128;
    const float* gB = g_B + bn * 128;
    #pragma unroll
    for (int it = 0; it < 16; ++it) {
        int idx = it * 256 + tid;              // float4 index over 128x32
        int k = idx >> 5, c4 = (idx & 31) << 2;
        *(float4*)&sA[k * 128 + c4] = *(const float4*)&gA[(size_t)k * M_TOT + c4];
        *(float4*)&sB[k * 128 + c4] = *(const float4*)&gB[(size_t)k * M_TOT + c4];
    }
    __syncthreads();

    int tx = tid & 15, ty = tid >> 4;
    unsigned long long acc[8][4];
    #pragma unroll
    for (int i = 0; i < 8; ++i)
        #pragma unroll
        for (int j = 0; j < 4; ++j) acc[i][j] = 0ull;

    #pragma unroll 4
    for (int k = 0; k < 128; ++k) {
        float4 a0 = *(float4*)&sA[k * 128 + ty * 8];
        float4 a1 = *(float4*)&sA[k * 128 + ty * 8 + 4];
        float4 b0 = *(float4*)&sB[k * 128 + tx * 8];
        float4 b1 = *(float4*)&sB[k * 128 + tx * 8 + 4];
        unsigned long long bp[4] = { pack2(b0.x, b0.y), pack2(b0.z, b0.w),
                                     pack2(b1.x, b1.y), pack2(b1.z, b1.w) };
        float av[8] = { a0.x, a0.y, a0.z, a0.w, a1.x, a1.y, a1.z, a1.w };
        #pragma unroll
        for (int i = 0; i < 8; ++i) {
            unsigned long long a2 = pack2(av[i], av[i]);
            #pragma unroll
            for (int j = 0; j < 4; ++j) ffma2(acc[i][j], a2, bp[j]);
        }
    }

    // Permuted store: (m,n) -> row r=(m/32)*256+(n/32), col c=(m%32)*32+(n%32)
    #pragma unroll
    for (int i = 0; i < 8; ++i) {
        int m = bm * 128 + ty * 8 + i;
        int ii = m >> 5, h = m & 31;
        #pragma unroll
        for (int j = 0; j < 4; ++j) {
            int n = bn * 128 + tx * 8 + j * 2;   // pair (n, n+1) stays within one 32-block
            int jj = n >> 5, kk = n & 31;
            size_t idx = (size_t)(ii * 256 + jj) * KK2 + h * 32 + kk;
            *(unsigned long long*)&g_outer[idx] = acc[i][j];   // float2 bits
        }
    }
}

// ---------------- GEMM2: out[r,p] = sum_c outer[r,c]*Wo[c,p] + bo[p] ----------------
// M=65536, N=64, K=1024. BM=128, BN=64, BK=32, double-buffered via register prefetch.
__global__ void __launch_bounds__(256) k_gemm2(
    const float* __restrict__ Wo, const float* __restrict__ bo, float* __restrict__ out)
{
    __shared__ float sA[2][128 * 32];   // [r][k]  16 KB each
    __shared__ float sW[2][32 * 64];    // [k][p]   8 KB each   (total 48 KB)
    int tid = threadIdx.x;
    int tx = tid & 15, ty = tid >> 4;
    const float* gO = g_outer + (size_t)blockIdx.x * 128 * KK2;

    // chunk 0
    #pragma unroll
    for (int it = 0; it < 4; ++it) {
        int idx = it * 256 + tid; int r = idx >> 3, c4 = (idx & 7) << 2;
        *(float4*)&sA[0][r * 32 + c4] = *(const float4*)&gO[(size_t)r * KK2 + c4];
    }
    #pragma unroll
    for (int it = 0; it < 2; ++it) {
        int idx = it * 256 + tid; int k = idx >> 4, p4 = (idx & 15) << 2;
        *(float4*)&sW[0][k * 64 + p4] = *(const float4*)&Wo[(size_t)k * 64 + p4];
    }
    __syncthreads();

    unsigned long long acc[8][2];
    #pragma unroll
    for (int i = 0; i < 8; ++i) { acc[i][0] = 0ull; acc[i][1] = 0ull; }

    float4 pfA[4]; float4 pfW[2];
    for (int ch = 0; ch < 32; ++ch) {
        int cur = ch & 1;
        if (ch < 31) {
            int kb = (ch + 1) * 32;
            #pragma unroll
            for (int it = 0; it < 4; ++it) {
                int idx = it * 256 + tid; int r = idx >> 3, c4 = (idx & 7) << 2;
                pfA[it] = *(const float4*)&gO[(size_t)r * KK2 + kb + c4];
            }
            #pragma unroll
            for (int it = 0; it < 2; ++it) {
                int idx = it * 256 + tid; int k = idx >> 4, p4 = (idx & 15) << 2;
                pfW[it] = *(const float4*)&Wo[(size_t)(kb + k) * 64 + p4];
            }
        }
        #pragma unroll
        for (int kk = 0; kk < 32; ++kk) {
            float4 w0 = *(float4*)&sW[cur][kk * 64 + tx * 4];
            unsigned long long w01 = pack2(w0.x, w0.y), w23 = pack2(w0.z, w0.w);
            #pragma unroll
            for (int i = 0; i < 8; ++i) {
                float av = sA[cur][(ty * 8 + i) * 32 + kk];   // 2-way broadcast
                unsigned long long a2 = pack2(av, av);
                ffma2(acc[i][0], a2, w01);
                ffma2(acc[i][1], a2, w23);
            }
        }
        if (ch < 31) {
            int nxt = cur ^ 1;
            #pragma unroll
            for (int it = 0; it < 4; ++it) {
                int idx = it * 256 + tid; int r = idx >> 3, c4 = (idx & 7) << 2;
                *(float4*)&sA[nxt][r * 32 + c4] = pfA[it];
            }
            #pragma unroll
            for (int it = 0; it < 2; ++it) {
                int idx = it * 256 + tid; int k = idx >> 4, p4 = (idx & 15) << 2;
                *(float4*)&sW[nxt][k * 64 + p4] = pfW[it];
            }
        }
        __syncthreads();
    }

    #pragma unroll
    for (int i = 0; i < 8; ++i) {
        size_t r = (size_t)blockIdx.x * 128 + ty * 8 + i;
        #pragma unroll
        for (int j = 0; j < 2; ++j) {
            float lo, hi; unpack2(acc[i][j], lo, hi);
            int p = tx * 4 + j * 2;
            float2 v = make_float2(lo + bo[p], hi + bo[p + 1]);
            *(float2*)&out[r * 64 + p] = v;
        }
    }
}

extern "C" void kernel_launch(void* const* d_in, const int* in_sizes, int n_in,
                              void* d_out, int out_size) {
    const float* msa   = (const float*)d_in[0];
    const float* mask  = (const float*)d_in[1];
    const float* gamma = (const float*)d_in[2];
    const float* beta  = (const float*)d_in[3];
    const float* Wa    = (const float*)d_in[4];
    const float* ba    = (const float*)d_in[5];
    const float* Wb    = (const float*)d_in[6];
    const float* bb    = (const float*)d_in[7];
    const float* Wo    = (const float*)d_in[8];
    const float* bo    = (const float*)d_in[9];
    float* out = (float*)d_out;

    cudaFuncSetAttribute(k_gemm1, cudaFuncAttributeMaxDynamicSharedMemorySize, 131072);

    k_denom<<<1, 256>>>(mask);
    k_prep<<<4096, 256>>>(msa, mask, gamma, beta, Wa, ba, Wb, bb);
    k_gemm1<<<dim3(64, 64), 256, 131072>>>();
    k_gemm2<<<512, 256>>>(Wo, bo, out);
}

// round 4
// speedup vs baseline: 1.4225x; 1.4225x over previous
#include <cuda_runtime.h>
#include <cuda_bf16.h>
#include <mma.h>
#include <cstdint>

using namespace nvcuda;

// Problem constants
#define SS_   128     // MSA depth S  (K of GEMM1)
#define NRES  256     // residues
#define DD    64      // msa dim
#define HH_   32      // proj dim H
#define M_TOT 8192    // N*H
#define KK2   1024    // H*H (K of GEMM2)

// ---------------- device scratch (allocation-free rule) ----------------
__device__ float g_A[SS_ * M_TOT];                  // [s][m] fp32 (prep out)
__device__ float g_B[SS_ * M_TOT];
__device__ __nv_bfloat16 g_Ah[M_TOT * SS_];         // [m][s] K-major bf16 hi/lo
__device__ __nv_bfloat16 g_Al[M_TOT * SS_];
__device__ __nv_bfloat16 g_Bh[M_TOT * SS_];
__device__ __nv_bfloat16 g_Bl[M_TOT * SS_];
__device__ __nv_bfloat16 g_Oh[(size_t)65536 * KK2]; // outer hi  [r][c]  128 MB
__device__ __nv_bfloat16 g_Ol[(size_t)65536 * KK2]; // outer lo  [r][c]  128 MB
__device__ __nv_bfloat16 g_Wh[64 * KK2];            // Wo^T hi  [p][c]
__device__ __nv_bfloat16 g_Wl[64 * KK2];
__device__ float g_invden[NRES];

__device__ __forceinline__ void split_bf16(float v, __nv_bfloat16& h, __nv_bfloat16& l) {
    h = __float2bfloat16(v);
    l = __float2bfloat16(v - __bfloat162float(h));
}

// ---------------- denom ----------------
__global__ void k_denom(const float* __restrict__ mask) {
    int i = threadIdx.x;
    float s = 0.f;
    #pragma unroll 8
    for (int t = 0; t < SS_; ++t) s += mask[t * NRES + i];
    g_invden[i] = 1.0f / fmaxf(s, 1.0f);
}

// ---------------- prep: LN + dual projection + mask + denom fold ----------------
__global__ void __launch_bounds__(256) k_prep(
    const float* __restrict__ x, const float* __restrict__ mask,
    const float* __restrict__ gamma, const float* __restrict__ beta,
    const float* __restrict__ Wa, const float* __restrict__ ba,
    const float* __restrict__ Wb, const float* __restrict__ bb)
{
    __shared__ float sx[8][64];
    int warp = threadIdx.x >> 5, lane = threadIdx.x & 31;
    int row = blockIdx.x * 8 + warp;          // row = s*256 + i
    const float* xr = x + (size_t)row * DD;

    float v0 = xr[lane], v1 = xr[lane + 32];
    float sum = v0 + v1;
    #pragma unroll
    for (int o = 16; o; o >>= 1) sum += __shfl_xor_sync(~0u, sum, o);
    float mu = sum * (1.0f / 64.0f);
    float d0 = v0 - mu, d1 = v1 - mu;
    float vs = d0 * d0 + d1 * d1;
    #pragma unroll
    for (int o = 16; o; o >>= 1) vs += __shfl_xor_sync(~0u, vs, o);
    float rstd = rsqrtf(vs * (1.0f / 64.0f) + 1e-5f);
    sx[warp][lane]      = d0 * rstd * gamma[lane]      + beta[lane];
    sx[warp][lane + 32] = d1 * rstd * gamma[lane + 32] + beta[lane + 32];
    __syncwarp();

    int s = row >> 8, i = row & 255;
    float m = mask[s * NRES + i];
    float a = ba[lane], b = bb[lane];
    #pragma unroll
    for (int d = 0; d < 64; ++d) {
        float xv = sx[warp][d];
        a = fmaf(xv, Wa[d * HH_ + lane], a);
        b = fmaf(xv, Wb[d * HH_ + lane], b);
    }
    a *= m * g_invden[i];
    b *= m;
    g_A[s * M_TOT + i * HH_ + lane] = a;
    g_B[s * M_TOT + i * HH_ + lane] = b;
}

// ---------------- transpose + split: fp32 [s][m] -> bf16 hi/lo [m][s] ----------------
__global__ void k_split_t() {
    __shared__ float t[32][33];
    const float* src = blockIdx.z ? g_B : g_A;
    __nv_bfloat16* oh = blockIdx.z ? g_Bh : g_Ah;
    __nv_bfloat16* ol = blockIdx.z ? g_Bl : g_Al;
    int tx = threadIdx.x, ty = threadIdx.y;
    #pragma unroll
    for (int k = 0; k < 4; ++k) {
        int s = blockIdx.y * 32 + ty + k * 8;
        int m = blockIdx.x * 32 + tx;
        t[ty + k * 8][tx] = src[(size_t)s * M_TOT + m];
    }
    __syncthreads();
    #pragma unroll
    for (int k = 0; k < 4; ++k) {
        int m = blockIdx.x * 32 + ty + k * 8;
        int s = blockIdx.y * 32 + tx;
        float v = t[tx][ty + k * 8];
        __nv_bfloat16 h, l; split_bf16(v, h, l);
        oh[(size_t)m * SS_ + s] = h;
        ol[(size_t)m * SS_ + s] = l;
    }
}

// ---------------- Wo transpose + split: [c][p] -> [p][c] bf16 hi/lo ----------------
__global__ void k_wsplit(const float* __restrict__ Wo) {
    int idx = blockIdx.x * 256 + threadIdx.x;     // 65536 total
    int p = idx >> 10, c = idx & 1023;
    float v = Wo[(size_t)c * 64 + p];
    __nv_bfloat16 h, l; split_bf16(v, h, l);
    g_Wh[idx] = h;
    g_Wl[idx] = l;
}

// ===================== GEMM1: outer = A^T B (WMMA bf16, 3-product) =====================
// M=N=8192, K=128. CTA 128x128, 8 warps (4m x 2n), warp 32x64.
// smem tiles: stride 72 bf16, K-chunk 64, 2 chunks.
#define SK1 72
#define G1_TILE (128 * SK1)           // elems per tile

__global__ void __launch_bounds__(256, 2) k_wg1() {
    extern __shared__ char smc[];
    __nv_bfloat16* sAh = (__nv_bfloat16*)smc;
    __nv_bfloat16* sAl = sAh + G1_TILE;
    __nv_bfloat16* sBh = sAl + G1_TILE;
    __nv_bfloat16* sBl = sBh + G1_TILE;
    float* sC = (float*)smc;           // 128 x 132 fp32 overlay (epilogue)

    int tid = threadIdx.x;
    int wid = tid >> 5;
    int wm = wid & 3, wn = wid >> 2;   // warp 32(m) x 64(n)
    int bm = blockIdx.x, bn = blockIdx.y;

    const __nv_bfloat16* gAh = g_Ah + (size_t)bm * 128 * SS_;
    const __nv_bfloat16* gAl = g_Al + (size_t)bm * 128 * SS_;
    const __nv_bfloat16* gBh = g_Bh + (size_t)bn * 128 * SS_;
    const __nv_bfloat16* gBl = g_Bl + (size_t)bn * 128 * SS_;

    wmma::fragment<wmma::accumulator, 16, 16, 16, float> acc[2][4];
    #pragma unroll
    for (int i = 0; i < 2; ++i)
        #pragma unroll
        for (int j = 0; j < 4; ++j) wmma::fill_fragment(acc[i][j], 0.0f);

    #pragma unroll
    for (int ch = 0; ch < 2; ++ch) {
        int kb = ch * 64;
        // load 4 tiles: 128 rows x 64 bf16 each
        #pragma unroll
        for (int it = 0; it < 4; ++it) {
            int idx = it * 256 + tid;        // 1024 segs
            int row = idx >> 3, seg = idx & 7;
            size_t go = (size_t)row * SS_ + kb + seg * 8;
            int so = row * SK1 + seg * 8;
            *(uint4*)(sAh + so) = *(const uint4*)(gAh + go);
            *(uint4*)(sAl + so) = *(const uint4*)(gAl + go);
            *(uint4*)(sBh + so) = *(const uint4*)(gBh + go);
            *(uint4*)(sBl + so) = *(const uint4*)(gBl + go);
        }
        __syncthreads();

        #pragma unroll
        for (int ks = 0; ks < 4; ++ks) {
            wmma::fragment<wmma::matrix_a, 16, 16, 16, __nv_bfloat16, wmma::row_major> ah[2], al[2];
            #pragma unroll
            for (int mf = 0; mf < 2; ++mf) {
                wmma::load_matrix_sync(ah[mf], sAh + (wm * 32 + mf * 16) * SK1 + ks * 16, SK1);
                wmma::load_matrix_sync(al[mf], sAl + (wm * 32 + mf * 16) * SK1 + ks * 16, SK1);
            }
            #pragma unroll
            for (int nf = 0; nf < 4; ++nf) {
                wmma::fragment<wmma::matrix_b, 16, 16, 16, __nv_bfloat16, wmma::col_major> bh, bl;
                wmma::load_matrix_sync(bh, sBh + (wn * 64 + nf * 16) * SK1 + ks * 16, SK1);
                wmma::mma_sync(acc[0][nf], ah[0], bh, acc[0][nf]);
                wmma::mma_sync(acc[1][nf], ah[1], bh, acc[1][nf]);
                wmma::mma_sync(acc[0][nf], al[0], bh, acc[0][nf]);
                wmma::mma_sync(acc[1][nf], al[1], bh, acc[1][nf]);
                wmma::load_matrix_sync(bl, sBl + (wn * 64 + nf * 16) * SK1 + ks * 16, SK1);
                wmma::mma_sync(acc[0][nf], ah[0], bl, acc[0][nf]);
                wmma::mma_sync(acc[1][nf], ah[1], bl, acc[1][nf]);
            }
        }
        __syncthreads();
    }

    // ---- epilogue: frags -> smem fp32 (stride 132) -> split bf16 hi/lo permuted store
    #pragma unroll
    for (int mf = 0; mf < 2; ++mf)
        #pragma unroll
        for (int nf = 0; nf < 4; ++nf)
            wmma::store_matrix_sync(sC + (wm * 32 + mf * 16) * 132 + wn * 64 + nf * 16,
                                    acc[mf][nf], 132, wmma::mem_row_major);
    __syncthreads();

    // out rows: r = (bm*4 + ii)*256 + (bn*4 + jj); col c = h*32 + kk
    // 16 rows x 1024 cols -> 2048 uint4 per precision
    #pragma unroll
    for (int it = 0; it < 8; ++it) {
        int idx = it * 256 + tid;
        int lrow = idx >> 7;               // 0..15 : ii*4 + jj
        int seg  = idx & 127;              // col segment of 8
        int ii = lrow >> 2, jj = lrow & 3;
        int c0 = seg * 8;
        int h = c0 >> 5, kk = c0 & 31;
        const float* p = sC + (ii * 32 + h) * 132 + jj * 32 + kk;
        uint32_t hp[4], lp[4];
        #pragma unroll
        for (int q = 0; q < 4; ++q) {
            float v0 = p[2 * q], v1 = p[2 * q + 1];
            __nv_bfloat16 h0, l0, h1, l1;
            split_bf16(v0, h0, l0);
            split_bf16(v1, h1, l1);
            hp[q] = (uint32_t)__bfloat16_as_ushort(h0) | ((uint32_t)__bfloat16_as_ushort(h1) << 16);
            lp[q] = (uint32_t)__bfloat16_as_ushort(l0) | ((uint32_t)__bfloat16_as_ushort(l1) << 16);
        }
        size_t r = (size_t)(bm * 4 + ii) * 256 + (bn * 4 + jj);
        size_t off = r * KK2 + c0;
        *(uint4*)(g_Oh + off) = make_uint4(hp[0], hp[1], hp[2], hp[3]);
        *(uint4*)(g_Ol + off) = make_uint4(lp[0], lp[1], lp[2], lp[3]);
    }
}

// ===================== GEMM2: out = outer @ Wo + bo (WMMA bf16, 3-product) =====================
// M=65536 (128/CTA), N=64, K=1024 in 16 chunks of 64. 8 warps (4m x 2n), warp 32x32.
#define SK2 72
#define G2_ATILE (128 * SK2)
#define G2_BTILE (64 * SK2)

__global__ void __launch_bounds__(256, 4) k_wg2(const float* __restrict__ bo,
                                                float* __restrict__ out) {
    extern __shared__ char smc[];
    __nv_bfloat16* sAh = (__nv_bfloat16*)smc;
    __nv_bfloat16* sAl = sAh + G2_ATILE;
    __nv_bfloat16* sBh = sAl + G2_ATILE;
    __nv_bfloat16* sBl = sBh + G2_BTILE;
    float* sC = (float*)smc;           // 128 x 68 fp32 overlay

    int tid = threadIdx.x;
    int wid = tid >> 5;
    int wm = wid & 3, wn = wid >> 2;   // warp 32(m) x 32(n)
    size_t rbase = (size_t)blockIdx.x * 128;

    wmma::fragment<wmma::accumulator, 16, 16, 16, float> acc[2][2];
    #pragma unroll
    for (int i = 0; i < 2; ++i)
        #pragma unroll
        for (int j = 0; j < 2; ++j) wmma::fill_fragment(acc[i][j], 0.0f);

    for (int ch = 0; ch < 16; ++ch) {
        int kb = ch * 64;
        #pragma unroll
        for (int it = 0; it < 4; ++it) {   // A: 128 rows x 64 bf16
            int idx = it * 256 + tid;
            int row = idx >> 3, seg = idx & 7;
            size_t go = (rbase + row) * KK2 + kb + seg * 8;
            int so = row * SK2 + seg * 8;
            *(uint4*)(sAh + so) = *(const uint4*)(g_Oh + go);
            *(uint4*)(sAl + so) = *(const uint4*)(g_Ol + go);
        }
        #pragma unroll
        for (int it = 0; it < 2; ++it) {   // B: 64 rows x 64 bf16
            int idx = it * 256 + tid;
            int row = idx >> 3, seg = idx & 7;
            size_t go = (size_t)row * KK2 + kb + seg * 8;
            int so = row * SK2 + seg * 8;
            *(uint4*)(sBh + so) = *(const uint4*)(g_Wh + go);
            *(uint4*)(sBl + so) = *(const uint4*)(g_Wl + go);
        }
        __syncthreads();

        #pragma unroll
        for (int ks = 0; ks < 4; ++ks) {
            wmma::fragment<wmma::matrix_a, 16, 16, 16, __nv_bfloat16, wmma::row_major> ah[2], al[2];
            #pragma unroll
            for (int mf = 0; mf < 2; ++mf) {
                wmma::load_matrix_sync(ah[mf], sAh + (wm * 32 + mf * 16) * SK2 + ks * 16, SK2);
                wmma::load_matrix_sync(al[mf], sAl + (wm * 32 + mf * 16) * SK2 + ks * 16, SK2);
            }
            #pragma unroll
            for (int nf = 0; nf < 2; ++nf) {
                wmma::fragment<wmma::matrix_b, 16, 16, 16, __nv_bfloat16, wmma::col_major> bh, bl;
                wmma::load_matrix_sync(bh, sBh + (wn * 32 + nf * 16) * SK2 + ks * 16, SK2);
                wmma::mma_sync(acc[0][nf], ah[0], bh, acc[0][nf]);
                wmma::mma_sync(acc[1][nf], ah[1], bh, acc[1][nf]);
                wmma::mma_sync(acc[0][nf], al[0], bh, acc[0][nf]);
                wmma::mma_sync(acc[1][nf], al[1], bh, acc[1][nf]);
                wmma::load_matrix_sync(bl, sBl + (wn * 32 + nf * 16) * SK2 + ks * 16, SK2);
                wmma::mma_sync(acc[0][nf], ah[0], bl, acc[0][nf]);
                wmma::mma_sync(acc[1][nf], ah[1], bl, acc[1][nf]);
            }
        }
        __syncthreads();
    }

    // ---- epilogue: frags -> smem fp32 (stride 68) -> +bo -> out
    #pragma unroll
    for (int mf = 0; mf < 2; ++mf)
        #pragma unroll
        for (int nf = 0; nf < 2; ++nf)
            wmma::store_matrix_sync(sC + (wm * 32 + mf * 16) * 68 + wn * 32 + nf * 16,
                                    acc[mf][nf], 68, wmma::mem_row_major);
    __syncthreads();

    #pragma unroll
    for (int it = 0; it < 8; ++it) {
        int idx = it * 256 + tid;
        int row = idx >> 4, seg = idx & 15;
        const float* p = sC + row * 68 + seg * 4;
        float4 bv = __ldg((const float4*)bo + seg);
        float4 o;
        o.x = p[0] + bv.x; o.y = p[1] + bv.y; o.z = p[2] + bv.z; o.w = p[3] + bv.w;
        *(float4*)(out + (rbase + row) * 64 + seg * 4) = o;
    }
}

extern "C" void kernel_launch(void* const* d_in, const int* in_sizes, int n_in,
                              void* d_out, int out_size) {
    const float* msa   = (const float*)d_in[0];
    const float* mask  = (const float*)d_in[1];
    const float* gamma = (const float*)d_in[2];
    const float* beta  = (const float*)d_in[3];
    const float* Wa    = (const float*)d_in[4];
    const float* ba    = (const float*)d_in[5];
    const float* Wb    = (const float*)d_in[6];
    const float* bb    = (const float*)d_in[7];
    const float* Wo    = (const float*)d_in[8];
    const float* bo    = (const float*)d_in[9];
    float* out = (float*)d_out;

    const int SM1 = 4 * G1_TILE * 2;                    // 73728 B (>= 128*132*4 overlay? 67584 yes)
    const int SM2 = (2 * G2_ATILE + 2 * G2_BTILE) * 2;  // 55296 B
    cudaFuncSetAttribute(k_wg1, cudaFuncAttributeMaxDynamicSharedMemorySize, SM1);
    cudaFuncSetAttribute(k_wg2, cudaFuncAttributeMaxDynamicSharedMemorySize, SM2);

    k_denom<<<1, 256>>>(mask);
    k_prep<<<4096, 256>>>(msa, mask, gamma, beta, Wa, ba, Wb, bb);
    k_split_t<<<dim3(256, 4, 2), dim3(32, 8)>>>();
    k_wsplit<<<256, 256>>>(Wo);
    k_wg1<<<dim3(64, 64), 256, SM1>>>();
    k_wg2<<<512, 256, SM2>>>(bo, out);
}